// round 3
// baseline (speedup 1.0000x reference)
#include <cuda_runtime.h>
#include <math.h>

#define BATCH 64
#define TSTEPS 1024
#define IND 64
#define HD 512
#define OUTD 64
#define NCTA 128
#define NTHR 512

typedef unsigned long long ull;

// ---------------- persistent device state (no allocations allowed) ----------
__device__ float g_h1[2][HD * BATCH];        // layout: [j>>2][b][j&3]  (float4 over j%4.. actually k4-major)
__device__ float g_h2[2][HD * BATCH];
__device__ float g_xT[TSTEPS * IND * BATCH]; // [t][k>>2][b][k&3]
__device__ unsigned g_gen;                   // barrier generation (monotonic across replays)
__device__ unsigned g_count;                 // barrier arrival count

// ---------------- grid-wide sense barrier (128 CTAs, 1/SM guaranteed) -------
__device__ __forceinline__ void grid_barrier() {
    __syncthreads();
    if (threadIdx.x == 0) {
        __threadfence();
        volatile unsigned* vg = &g_gen;
        unsigned my = *vg;
        if (atomicAdd(&g_count, 1u) == NCTA - 1u) {
            g_count = 0u;
            __threadfence();
            *vg = my + 1u;
        } else {
            while (*vg == my) { }
        }
        __threadfence();
    }
    __syncthreads();
}

__device__ __forceinline__ float sigf(float x) { return 1.0f / (1.0f + __expf(-x)); }

// ---------------- packed f32x2 helpers (PTX-only path on sm_103a) -----------
__device__ __forceinline__ ull splat2(float v) {
    ull r; asm("mov.b64 %0, {%1, %1};" : "=l"(r) : "f"(v)); return r;
}
__device__ __forceinline__ void ffma2(ull& d, ull a, ull b) {
    asm("fma.rn.f32x2 %0, %1, %2, %0;" : "+l"(d) : "l"(a), "l"(b));
}
__device__ __forceinline__ ull addf2(ull a, ull b) {
    ull r; asm("add.rn.f32x2 %0, %1, %2;" : "=l"(r) : "l"(a), "l"(b)); return r;
}
__device__ __forceinline__ void unpack2(ull v, float& lo, float& hi) {
    asm("mov.b64 {%0, %1}, %2;" : "=f"(lo), "=f"(hi) : "l"(v));
}

// ---------------- shared memory layout (float offsets) ----------------------
// Weights interleaved per gate-pair: [jj][pair][k][e], e in {0,1} = gate pair*2+e.
// jj stride padded (+8 floats) so the 4 jj lanes hit distinct bank groups.
#define O_WA    0       // layer1: 4 * (2*576*2 + 8) = 9248
#define WA_JSTR 2312
#define O_WB    9248    // layer2: 4 * (2*1024*2 + 8) = 16416
#define WB_JSTR 4104
#define O_BA    25664   // 16: [jj][pair][e]
#define O_BB    25680   // 16
#define O_WO    25696   // 512
#define O_BO    26208   // 4
#define O_RED   26212   // 8 * 64 y-head reduction
#define O_PART  26724   // 256 * 4 floats: phase k-split partials (16B aligned)
#define SMEM_N  30000   // 120000 B > 114 KB -> guarantees 1 CTA/SM

// 4 k-steps: 16 MACs as 8 packed FFMA2 + 4 LDS.128 + shared splats
__device__ __forceinline__ void mac4(float4 v, const ull* wif, const ull* wgo,
                                     ull& aif, ull& ago) {
    ull s0 = splat2(v.x), s1 = splat2(v.y), s2 = splat2(v.z), s3 = splat2(v.w);
    ulonglong2 w0 = *(const ulonglong2*)(wif);
    ulonglong2 w1 = *(const ulonglong2*)(wif + 2);
    ulonglong2 u0 = *(const ulonglong2*)(wgo);
    ulonglong2 u1 = *(const ulonglong2*)(wgo + 2);
    ffma2(aif, w0.x, s0); ffma2(ago, u0.x, s0);
    ffma2(aif, w0.y, s1); ffma2(ago, u0.y, s1);
    ffma2(aif, w1.x, s2); ffma2(ago, u1.x, s2);
    ffma2(aif, w1.y, s3); ffma2(ago, u1.y, s3);
}

// y(t) head: CTA c (<64) owns output column c; 8 threads per batch split K.
__device__ __forceinline__ void do_y(int t, const float4* __restrict__ h2v,
                                     int c, int tid,
                                     const float* sWO, const float* sBO,
                                     float* sRed, float* __restrict__ out) {
    int b = tid & 63, u = tid >> 6;     // u in 0..7
    if (c < OUTD) {
        float p = 0.0f;
        int k4b = u * 16;
#pragma unroll
        for (int k4 = 0; k4 < 16; ++k4) {
            float4 v = h2v[(k4b + k4) * 64 + b];
            const float* w = sWO + (k4b + k4) * 4;
            p += v.x * w[0] + v.y * w[1] + v.z * w[2] + v.w * w[3];
        }
        sRed[u * 64 + b] = p;
    }
    __syncthreads();
    if (c < OUTD && u == 0) {
        float y = sBO[0];
#pragma unroll
        for (int m = 0; m < 8; ++m) y += sRed[m * 64 + b];
        out[b * (TSTEPS * OUTD) + t * OUTD + c] = y;
    }
}

extern __shared__ float smem[];

__global__ void __launch_bounds__(NTHR, 1)
lstm_persistent_kernel(const float* __restrict__ x,
                       const float* __restrict__ Wih1, const float* __restrict__ Whh1,
                       const float* __restrict__ bih1, const float* __restrict__ bhh1,
                       const float* __restrict__ Wih2, const float* __restrict__ Whh2,
                       const float* __restrict__ bih2, const float* __restrict__ bhh2,
                       const float* __restrict__ Wout, const float* __restrict__ bout,
                       float* __restrict__ out) {
    float* sWA = smem + O_WA;
    float* sWB = smem + O_WB;
    float* sBA = smem + O_BA;
    float* sBB = smem + O_BB;
    float* sWO = smem + O_WO;
    float* sBO = smem + O_BO;
    float* sRed = smem + O_RED;
    ulonglong2* sPartV = (ulonglong2*)(smem + O_PART);

    const int tid  = threadIdx.x;
    const int c    = blockIdx.x;          // CTA owns h columns j0..j0+3
    const int j0   = c * 4;
    const int lane = tid & 31;
    const int jj   = lane & 3;            // j within CTA (4 lanes dup per b)
    const int warp = tid >> 5;
    const int kh   = warp & 1;            // k-split half
    const int b    = (lane >> 2) + ((warp >> 1) << 3);  // batch 0..63
    const int idx  = ((warp >> 1) << 5) + lane;         // 0..255, same for kh pair

    // ---- load weights into interleaved, padded SMEM (once) ----
    for (int i = tid; i < 9216; i += NTHR) {
        int jw = i / 2304, r1 = i - jw * 2304;
        int p = r1 / 1152, r2 = r1 - p * 1152;
        int k = r2 >> 1, e = r2 & 1;
        int row = (p * 2 + e) * HD + j0 + jw;
        sWA[jw * WA_JSTR + p * 1152 + k * 2 + e] =
            (k < IND) ? Wih1[row * IND + k] : Whh1[row * HD + (k - IND)];
    }
    for (int i = tid; i < 16384; i += NTHR) {
        int jw = i >> 12, r1 = i & 4095;
        int p = r1 >> 11, r2 = r1 & 2047;
        int k = r2 >> 1, e = r2 & 1;
        int row = (p * 2 + e) * HD + j0 + jw;
        sWB[jw * WB_JSTR + p * 2048 + k * 2 + e] =
            (k < HD) ? Wih2[row * HD + k] : Whh2[row * HD + (k - HD)];
    }
    if (tid < 16) {
        int jw = tid >> 2, p = (tid >> 1) & 1, e = tid & 1;
        int row = (p * 2 + e) * HD + j0 + jw;
        sBA[jw * 4 + p * 2 + e] = bih1[row] + bhh1[row];
        sBB[jw * 4 + p * 2 + e] = bih2[row] + bhh2[row];
    }
    if (c < OUTD) {
        for (int i = tid; i < HD; i += NTHR) sWO[i] = Wout[c * HD + i];
        if (tid == 0) sBO[0] = bout[c];
    }

    // ---- prologue: transpose x to [t][k/4][b][k%4]; zero h buffers ----
    for (int t = c * (TSTEPS / NCTA); t < (c + 1) * (TSTEPS / NCTA); ++t) {
        for (int i = tid; i < BATCH * IND; i += NTHR) {
            int bb = i >> 6, k = i & 63;
            g_xT[((t * 16 + (k >> 2)) * 64 + bb) * 4 + (k & 3)] =
                x[bb * (TSTEPS * IND) + t * IND + k];
        }
    }
    {
        int gi = c * NTHR + tid;
        if (gi < HD * BATCH) {
            g_h1[0][gi] = 0.0f; g_h1[1][gi] = 0.0f;
            g_h2[0][gi] = 0.0f; g_h2[1][gi] = 0.0f;
        }
    }
    grid_barrier();

    // ---- per-thread constant pointers ----
    const ull* wifA = (const ull*)(sWA + jj * WA_JSTR);
    const ull* wgoA = (const ull*)(sWA + jj * WA_JSTR + 1152);
    const ull* wifB = (const ull*)(sWB + jj * WB_JSTR);
    const ull* wgoB = (const ull*)(sWB + jj * WB_JSTR + 2048);
    const ull biasIF1 = *(const ull*)(sBA + jj * 4);
    const ull biasGO1 = *(const ull*)(sBA + jj * 4 + 2);
    const ull biasIF2 = *(const ull*)(sBB + jj * 4);
    const ull biasGO2 = *(const ull*)(sBB + jj * 4 + 2);
    const int hstore = c * 256 + b * 4 + jj;   // [j>>2][b][j&3]

    float c1 = 0.0f, c2 = 0.0f;

    for (int t = 0; t < TSTEPS; ++t) {
        const int rp = t & 1, wb2 = rp ^ 1;
        const float4* h1r = (const float4*)g_h1[rp];
        const float4* h2r = (const float4*)g_h2[rp];

        // ---- phase A: gates1 = x_t W_ih1^T + h1 W_hh1^T + bias (k-split) ----
        ull aif = kh ? 0ull : biasIF1;
        ull ago = kh ? 0ull : biasGO1;
        if (kh == 0) {
            const float4* xr = (const float4*)g_xT + t * (16 * 64);
#pragma unroll
            for (int k4 = 0; k4 < 16; ++k4)
                mac4(xr[k4 * 64 + b], wifA + 4 * k4, wgoA + 4 * k4, aif, ago);
#pragma unroll 4
            for (int k4 = 0; k4 < 56; ++k4)
                mac4(h1r[k4 * 64 + b], wifA + 4 * (16 + k4), wgoA + 4 * (16 + k4), aif, ago);
        } else {
#pragma unroll 4
            for (int k4 = 56; k4 < 128; ++k4)
                mac4(h1r[k4 * 64 + b], wifA + 4 * (16 + k4), wgoA + 4 * (16 + k4), aif, ago);
        }
        if (kh) sPartV[idx] = make_ulonglong2(aif, ago);
        __syncthreads();
        if (!kh) {
            ulonglong2 pp = sPartV[idx];
            aif = addf2(aif, pp.x);
            ago = addf2(ago, pp.y);
            float gi, gf, gg, go_;
            unpack2(aif, gi, gf);
            unpack2(ago, gg, go_);
            c1 = sigf(gf) * c1 + sigf(gi) * tanhf(gg);
            g_h1[wb2][hstore] = sigf(go_) * tanhf(c1);
        }

        grid_barrier();   // publish h1(t)

        // ---- deferred output head y(t-1): reads h2(t-1) = g_h2[rp] ----
        if (t > 0) do_y(t - 1, h2r, c, tid, sWO, sBO, sRed, out);

        // ---- phase B: gates2 = h1(t) W_ih2^T + h2(t-1) W_hh2^T + bias ----
        ull bif = kh ? 0ull : biasIF2;
        ull bgo = kh ? 0ull : biasGO2;
        if (kh == 0) {
            const float4* h1w = (const float4*)g_h1[wb2];
#pragma unroll 4
            for (int k4 = 0; k4 < 128; ++k4)
                mac4(h1w[k4 * 64 + b], wifB + 4 * k4, wgoB + 4 * k4, bif, bgo);
        } else {
#pragma unroll 4
            for (int k4 = 0; k4 < 128; ++k4)
                mac4(h2r[k4 * 64 + b], wifB + 4 * (128 + k4), wgoB + 4 * (128 + k4), bif, bgo);
        }
        if (kh) sPartV[idx] = make_ulonglong2(bif, bgo);
        __syncthreads();
        if (!kh) {
            ulonglong2 pp = sPartV[idx];
            bif = addf2(bif, pp.x);
            bgo = addf2(bgo, pp.y);
            float gi, gf, gg, go_;
            unpack2(bif, gi, gf);
            unpack2(bgo, gg, go_);
            c2 = sigf(gf) * c2 + sigf(gi) * tanhf(gg);
            g_h2[wb2][hstore] = sigf(go_) * tanhf(c2);
        }
        __syncthreads();  // sPart safe for next phase-A write
    }

    grid_barrier();
    // final head: h2(T-1) lives in buffer ((T-1)&1)^1 == 0
    do_y(TSTEPS - 1, (const float4*)g_h2[0], c, tid, sWO, sBO, sRed, out);
}

extern "C" void kernel_launch(void* const* d_in, const int* in_sizes, int n_in,
                              void* d_out, int out_size) {
    const float* x    = (const float*)d_in[0];
    const float* Wih1 = (const float*)d_in[1];
    const float* Whh1 = (const float*)d_in[2];
    const float* bih1 = (const float*)d_in[3];
    const float* bhh1 = (const float*)d_in[4];
    const float* Wih2 = (const float*)d_in[5];
    const float* Whh2 = (const float*)d_in[6];
    const float* bih2 = (const float*)d_in[7];
    const float* bhh2 = (const float*)d_in[8];
    const float* Wout = (const float*)d_in[9];
    const float* bout = (const float*)d_in[10];
    float* out = (float*)d_out;

    size_t smem_bytes = (size_t)SMEM_N * sizeof(float);
    cudaFuncSetAttribute(lstm_persistent_kernel,
                         cudaFuncAttributeMaxDynamicSharedMemorySize,
                         (int)smem_bytes);
    lstm_persistent_kernel<<<NCTA, NTHR, smem_bytes>>>(
        x, Wih1, Whh1, bih1, bhh1, Wih2, Whh2, bih2, bhh2, Wout, bout, out);
}

// round 4
// speedup vs baseline: 1.2863x; 1.2863x over previous
#include <cuda_runtime.h>
#include <math.h>

#define BATCH 64
#define TSTEPS 1024
#define IND 64
#define HD 512
#define OUTD 64
#define NCTA 128
#define NTHR 256

typedef unsigned long long ull;

// ---------------- persistent device state ----------------
__device__ __align__(16) float g_h1[2][HD * BATCH];   // [j][b], b contiguous
__device__ __align__(16) float g_h2[2][HD * BATCH];
__device__ __align__(16) float g_xT[TSTEPS * IND * BATCH]; // [t][k][b]
__device__ unsigned g_gen;
__device__ unsigned g_count;

// ---------------- grid-wide sense barrier ----------------
__device__ __forceinline__ void grid_barrier() {
    __syncthreads();
    if (threadIdx.x == 0) {
        __threadfence();
        volatile unsigned* vg = &g_gen;
        unsigned my = *vg;
        if (atomicAdd(&g_count, 1u) == NCTA - 1u) {
            g_count = 0u;
            __threadfence();
            *vg = my + 1u;
        } else {
            while (*vg == my) { }
        }
        __threadfence();
    }
    __syncthreads();
}

__device__ __forceinline__ float sigf(float x) { return 1.0f / (1.0f + __expf(-x)); }

// ---------------- packed f32x2 helpers ----------------
__device__ __forceinline__ ull splat2(float v) {
    ull r; asm("mov.b64 %0, {%1, %1};" : "=l"(r) : "f"(v)); return r;
}
__device__ __forceinline__ ull pack2(float lo, float hi) {
    ull r; asm("mov.b64 %0, {%1, %2};" : "=l"(r) : "f"(lo), "f"(hi)); return r;
}
__device__ __forceinline__ void ffma2(ull& d, ull a, ull b) {
    asm("fma.rn.f32x2 %0, %1, %2, %0;" : "+l"(d) : "l"(a), "l"(b));
}
__device__ __forceinline__ ull addf2(ull a, ull b) {
    ull r; asm("add.rn.f32x2 %0, %1, %2;" : "=l"(r) : "l"(a), "l"(b)); return r;
}
__device__ __forceinline__ void unpack2(ull v, float& lo, float& hi) {
    asm("mov.b64 {%0, %1}, %2;" : "=f"(lo), "=f"(hi) : "l"(v));
}

// ---------------- SMEM layout (byte offsets) ----------------
// sWA: 576 k * 16 ull (splatted, [k][jj][type])   = 73728 B
// sWB: 1024 k * 16 ull                            = 131072 B
// sRed: ulonglong2[8][128] reduction buffer       = 16384 B
// sBA/sBB: 16 ull each (splatted biases)          = 256 B
// sWO: 512 floats; sBO: 1 float; sRY: 256 floats
#define O_WA   0
#define O_WB   73728
#define O_RED  204800
#define O_BA   221184
#define O_BB   221312
#define O_WO   221440
#define O_BO   223488
#define O_RY   223504
#define SMEM_BYTES 224544

// k-block MAC: per k: 2 LDS.128 (splatted weights) + 2 LDG.128 (h pairs) + 16 FFMA2
__device__ __forceinline__ void mac_block(const ull* __restrict__ wbase,
                                          const float* __restrict__ hsrc,
                                          int n, int jj, int bgrp,
                                          ull (&acc)[4][4]) {
#pragma unroll 4
    for (int k = 0; k < n; ++k) {
        const ulonglong2* wp = (const ulonglong2*)(wbase + k * 16 + jj * 4);
        ulonglong2 wif = wp[0];                  // {i,i},{f,f}
        ulonglong2 wgo = wp[1];                  // {g,g},{o,o}
        const ulonglong2* hp = (const ulonglong2*)(hsrc + k * 64 + bgrp * 8);
        ulonglong2 hA = hp[0], hB = hp[1];       // 4 b-pairs
        ffma2(acc[0][0], wif.x, hA.x); ffma2(acc[0][1], wif.y, hA.x);
        ffma2(acc[0][2], wgo.x, hA.x); ffma2(acc[0][3], wgo.y, hA.x);
        ffma2(acc[1][0], wif.x, hA.y); ffma2(acc[1][1], wif.y, hA.y);
        ffma2(acc[1][2], wgo.x, hA.y); ffma2(acc[1][3], wgo.y, hA.y);
        ffma2(acc[2][0], wif.x, hB.x); ffma2(acc[2][1], wif.y, hB.x);
        ffma2(acc[2][2], wgo.x, hB.x); ffma2(acc[2][3], wgo.y, hB.x);
        ffma2(acc[3][0], wif.x, hB.y); ffma2(acc[3][1], wif.y, hB.y);
        ffma2(acc[3][2], wgo.x, hB.y); ffma2(acc[3][3], wgo.y, hB.y);
    }
}

// 3-round SMEM tree reduction over the 8 k-slices (warp index = slice).
// Layout acc-index-major: sRed[i][slot] so STS/LDS.128 are conflict-free.
__device__ __forceinline__ void reduce_acc(ull (&acc)[4][4],
                                           ulonglong2 (*sRed)[128],
                                           int warp, int lane) {
    if (warp >= 4) {
        int slot = (warp - 4) * 32 + lane;
#pragma unroll
        for (int i = 0; i < 4; ++i) {
            sRed[i * 2][slot]     = make_ulonglong2(acc[i][0], acc[i][1]);
            sRed[i * 2 + 1][slot] = make_ulonglong2(acc[i][2], acc[i][3]);
        }
    }
    __syncthreads();
    if (warp < 4) {
        int slot = warp * 32 + lane;
#pragma unroll
        for (int i = 0; i < 4; ++i) {
            ulonglong2 a = sRed[i * 2][slot], b = sRed[i * 2 + 1][slot];
            acc[i][0] = addf2(acc[i][0], a.x); acc[i][1] = addf2(acc[i][1], a.y);
            acc[i][2] = addf2(acc[i][2], b.x); acc[i][3] = addf2(acc[i][3], b.y);
        }
    }
    __syncthreads();
    if (warp >= 1 && warp < 4) {
        int slot = (warp - 1) * 32 + lane;
#pragma unroll
        for (int i = 0; i < 4; ++i) {
            sRed[i * 2][slot]     = make_ulonglong2(acc[i][0], acc[i][1]);
            sRed[i * 2 + 1][slot] = make_ulonglong2(acc[i][2], acc[i][3]);
        }
    }
    __syncthreads();
    if (warp == 0) {
#pragma unroll
        for (int w = 0; w < 3; ++w) {
            int slot = w * 32 + lane;
#pragma unroll
            for (int i = 0; i < 4; ++i) {
                ulonglong2 a = sRed[i * 2][slot], b = sRed[i * 2 + 1][slot];
                acc[i][0] = addf2(acc[i][0], a.x); acc[i][1] = addf2(acc[i][1], a.y);
                acc[i][2] = addf2(acc[i][2], b.x); acc[i][3] = addf2(acc[i][3], b.y);
            }
        }
    }
}

// activations + cell update + h store (warp 0 lanes only)
__device__ __forceinline__ void cell_update(ull (&acc)[4][4], ull (&cc)[4],
                                            float* __restrict__ hdst,
                                            int j0, int jj, int bgrp) {
    ull hout[4];
#pragma unroll
    for (int bp = 0; bp < 4; ++bp) {
        float gi0, gi1, gf0, gf1, gg0, gg1, go0, go1, c0, c1;
        unpack2(acc[bp][0], gi0, gi1);
        unpack2(acc[bp][1], gf0, gf1);
        unpack2(acc[bp][2], gg0, gg1);
        unpack2(acc[bp][3], go0, go1);
        unpack2(cc[bp], c0, c1);
        c0 = sigf(gf0) * c0 + sigf(gi0) * tanhf(gg0);
        c1 = sigf(gf1) * c1 + sigf(gi1) * tanhf(gg1);
        float h0 = sigf(go0) * tanhf(c0);
        float h1 = sigf(go1) * tanhf(c1);
        cc[bp] = pack2(c0, c1);
        hout[bp] = pack2(h0, h1);
    }
    ulonglong2* hd = (ulonglong2*)(hdst + (j0 + jj) * 64 + bgrp * 8);
    hd[0] = make_ulonglong2(hout[0], hout[1]);
    hd[1] = make_ulonglong2(hout[2], hout[3]);
}

// y(t) head: CTA c (<64) owns output column c; 4-way k split.
__device__ __forceinline__ void do_y(int t, const float* __restrict__ h2v,
                                     int c, int tid,
                                     const float* sWO, const float* sBO,
                                     float* sRY, float* __restrict__ out) {
    int b = tid & 63, u = tid >> 6;   // u in 0..3
    if (c < OUTD) {
        float p = 0.0f;
        int k0 = u * 128;
#pragma unroll 8
        for (int k = 0; k < 128; ++k)
            p += h2v[(k0 + k) * 64 + b] * sWO[k0 + k];
        sRY[u * 64 + b] = p;
    }
    __syncthreads();
    if (c < OUTD && u == 0) {
        float y = sRY[b] + sRY[64 + b] + sRY[128 + b] + sRY[192 + b] + sBO[0];
        out[b * (TSTEPS * OUTD) + t * OUTD + c] = y;
    }
}

extern __shared__ char smem[];

__global__ void __launch_bounds__(NTHR, 1)
lstm_persistent_kernel(const float* __restrict__ x,
                       const float* __restrict__ Wih1, const float* __restrict__ Whh1,
                       const float* __restrict__ bih1, const float* __restrict__ bhh1,
                       const float* __restrict__ Wih2, const float* __restrict__ Whh2,
                       const float* __restrict__ bih2, const float* __restrict__ bhh2,
                       const float* __restrict__ Wout, const float* __restrict__ bout,
                       float* __restrict__ out) {
    ull* sWA = (ull*)(smem + O_WA);
    ull* sWB = (ull*)(smem + O_WB);
    ulonglong2 (*sRed)[128] = (ulonglong2(*)[128])(smem + O_RED);
    ull* sBA = (ull*)(smem + O_BA);
    ull* sBB = (ull*)(smem + O_BB);
    float* sWO = (float*)(smem + O_WO);
    float* sBO = (float*)(smem + O_BO);
    float* sRY = (float*)(smem + O_RY);

    const int tid  = threadIdx.x;
    const int c    = blockIdx.x;         // CTA owns j = c*4 .. c*4+3
    const int j0   = c * 4;
    const int warp = tid >> 5;           // = k-slice (0..7)
    const int lane = tid & 31;
    const int bgrp = lane >> 2;          // 0..7 : batch group (8 b each)
    const int jj   = lane & 3;           // which owned j column

    // ---- stage splatted weights into SMEM (once) ----
    for (int i = tid; i < 576 * 16; i += NTHR) {
        int k = i >> 4, r = i & 15, jw = r >> 2, tp = r & 3;
        int row = tp * HD + j0 + jw;
        float v = (k < IND) ? Wih1[row * IND + k] : Whh1[row * HD + (k - IND)];
        sWA[i] = splat2(v);
    }
    for (int i = tid; i < 1024 * 16; i += NTHR) {
        int k = i >> 4, r = i & 15, jw = r >> 2, tp = r & 3;
        int row = tp * HD + j0 + jw;
        float v = (k < HD) ? Wih2[row * HD + k] : Whh2[row * HD + (k - HD)];
        sWB[i] = splat2(v);
    }
    if (tid < 16) {
        int jw = tid >> 2, tp = tid & 3;
        int row = tp * HD + j0 + jw;
        sBA[tid] = splat2(bih1[row] + bhh1[row]);
        sBB[tid] = splat2(bih2[row] + bhh2[row]);
    }
    if (c < OUTD) {
        for (int i = tid; i < HD; i += NTHR) sWO[i] = Wout[c * HD + i];
        if (tid == 0) sBO[0] = bout[c];
    }

    // ---- prologue: x -> [t][k][b]; zero h buffers ----
    for (int t = c * (TSTEPS / NCTA); t < (c + 1) * (TSTEPS / NCTA); ++t) {
        for (int i = tid; i < BATCH * IND; i += NTHR) {
            int b = i & 63, k = i >> 6;
            g_xT[t * (IND * BATCH) + k * 64 + b] = x[b * (TSTEPS * IND) + t * IND + k];
        }
    }
    {
        int gi = c * NTHR + tid;     // 32768 threads cover HD*BATCH
        g_h1[0][gi] = 0.0f; g_h1[1][gi] = 0.0f;
        g_h2[0][gi] = 0.0f; g_h2[1][gi] = 0.0f;
    }
    grid_barrier();

    ull cc1[4] = {0, 0, 0, 0}, cc2[4] = {0, 0, 0, 0};
    const ull biasA[4] = { sBA[jj * 4], sBA[jj * 4 + 1], sBA[jj * 4 + 2], sBA[jj * 4 + 3] };
    const ull biasB[4] = { sBB[jj * 4], sBB[jj * 4 + 1], sBB[jj * 4 + 2], sBB[jj * 4 + 3] };

    for (int t = 0; t < TSTEPS; ++t) {
        const int rp = t & 1, wb2 = rp ^ 1;
        const float* h1r = g_h1[rp];
        const float* h2r = g_h2[rp];
        const float* h1w = g_h1[wb2];

        // ======== phase A: gates1 = x_t W_ih1^T + h1 W_hh1^T + b ========
        ull acc[4][4];
#pragma unroll
        for (int i = 0; i < 4; ++i)
#pragma unroll
            for (int p = 0; p < 4; ++p)
                acc[i][p] = (warp == 0) ? biasA[p] : 0ull;

        if (warp == 0) {
            mac_block(sWA, g_xT + t * (IND * BATCH), 64, jj, bgrp, acc);
            mac_block(sWA + 64 * 16, h1r, 8, jj, bgrp, acc);
        } else {
            mac_block(sWA + (72 * warp) * 16, h1r + (72 * warp - 64) * 64, 72, jj, bgrp, acc);
        }
        reduce_acc(acc, sRed, warp, lane);
        if (warp == 0) cell_update(acc, cc1, g_h1[wb2], j0, jj, bgrp);

        grid_barrier();   // publish h1(t); the ONLY grid barrier per step

        // deferred y(t-1) from h2(t-1)
        if (t > 0) do_y(t - 1, h2r, c, tid, sWO, sBO, sRY, out);

        // ======== phase B: gates2 = h1(t) W_ih2^T + h2(t-1) W_hh2^T + b ========
#pragma unroll
        for (int i = 0; i < 4; ++i)
#pragma unroll
            for (int p = 0; p < 4; ++p)
                acc[i][p] = (warp == 0) ? biasB[p] : 0ull;

        if (warp < 4) {
            mac_block(sWB + (128 * warp) * 16, h1w + (128 * warp) * 64, 128, jj, bgrp, acc);
        } else {
            mac_block(sWB + (128 * warp) * 16, h2r + (128 * warp - 512) * 64, 128, jj, bgrp, acc);
        }
        reduce_acc(acc, sRed, warp, lane);
        if (warp == 0) cell_update(acc, cc2, g_h2[wb2], j0, jj, bgrp);
    }

    grid_barrier();
    // final head: h2(T-1) is in buffer ((T-1)&1)^1 == 0
    do_y(TSTEPS - 1, g_h2[0], c, tid, sWO, sBO, sRY, out);
}

extern "C" void kernel_launch(void* const* d_in, const int* in_sizes, int n_in,
                              void* d_out, int out_size) {
    const float* x    = (const float*)d_in[0];
    const float* Wih1 = (const float*)d_in[1];
    const float* Whh1 = (const float*)d_in[2];
    const float* bih1 = (const float*)d_in[3];
    const float* bhh1 = (const float*)d_in[4];
    const float* Wih2 = (const float*)d_in[5];
    const float* Whh2 = (const float*)d_in[6];
    const float* bih2 = (const float*)d_in[7];
    const float* bhh2 = (const float*)d_in[8];
    const float* Wout = (const float*)d_in[9];
    const float* bout = (const float*)d_in[10];
    float* out = (float*)d_out;

    cudaFuncSetAttribute(lstm_persistent_kernel,
                         cudaFuncAttributeMaxDynamicSharedMemorySize, SMEM_BYTES);
    lstm_persistent_kernel<<<NCTA, NTHR, SMEM_BYTES>>>(
        x, Wih1, Whh1, bih1, bhh1, Wih2, Whh2, bih2, bhh2, Wout, bout, out);
}